// round 6
// baseline (speedup 1.0000x reference)
#include <cuda_runtime.h>

// SCVC: out[n, g*OG+o, p, q] = C[g,o]*x[n,g,p]*y[n,g,q] + a[n,g,o,p] + b[n,g,o,q]
//   a[p] = wA0*x[p-1] + wA1*x[p+1]  (zero boundary)
//   b[q] = wB0*y[q-1] + wB1*y[q+1]  (zero boundary)
// Shapes: N=8, G=8, OG=16, DX=DY=256. Output = 256 MiB fp32 -> store-bound.
// R6: one block per (n, g, p-tile), looping all 16 o. y staged once, b[q]
// computed in registers -> barrier-free o-loop, prologue amortized 16x.

#define N_  8
#define G_  8
#define OG_ 16
#define DX_ 256
#define DY_ 256
#define PT  16   // p-rows per block

__global__ __launch_bounds__(256) void scvc_kernel(
    const float* __restrict__ x,   // (N, G, DX)
    const float* __restrict__ y,   // (N, G, DY)
    const float* __restrict__ C,   // (G, OG)
    const float* __restrict__ wA,  // (G, OG, 2)
    const float* __restrict__ wB,  // (G, OG, 2)
    float* __restrict__ out)       // (N, G*OG, DX, DY)
{
    __shared__ float sy[DY_];
    __shared__ float swt[OG_][5];   // [o] = {C, wA0, wA1, wB0, wB1}

    const int b  = blockIdx.x;
    const int pt = b & 15;          // DX_/PT = 16 tiles
    const int g  = (b >> 4) & 7;    // G_ = 8
    const int n  = b >> 7;          // N_ = 8

    const int tid = threadIdx.x;
    const int ng  = n * G_ + g;

    // Stage y row.
    sy[tid] = y[ng * DY_ + tid];

    // Stage per-o weights (80 floats).
    if (tid < OG_ * 5) {
        const int o = tid / 5, w = tid % 5;
        const int go = g * OG_ + o;
        float v;
        if (w == 0)      v = C[go];
        else if (w <= 2) v = wA[go * 2 + (w - 1)];
        else             v = wB[go * 2 + (w - 3)];
        swt[o][w] = v;
    }

    // Per-thread x values for its 4 rows (registers, reused across all o).
    const int r = tid >> 6;         // row-within-4
    const int c = tid & 63;         // float4 column
    float xp[4], xl[4], xr[4];
    const float* __restrict__ xrow = x + ng * DX_;
    #pragma unroll
    for (int it = 0; it < 4; ++it) {
        const int p = pt * PT + it * 4 + r;
        xp[it] = xrow[p];
        xl[it] = (p > 0)       ? xrow[p - 1] : 0.0f;
        xr[it] = (p < DX_ - 1) ? xrow[p + 1] : 0.0f;
    }
    __syncthreads();

    // y fragment for this thread's 4 q positions, plus halo for b[q].
    const float4 yv  = reinterpret_cast<const float4*>(sy)[c];
    const float  yl0 = (c > 0)  ? sy[4 * c - 1] : 0.0f;   // y[q0-1]
    const float  yr3 = (c < 63) ? sy[4 * c + 4] : 0.0f;   // y[q3+1]

    float* __restrict__ obase_ng =
        out + (size_t)ng * OG_ * (size_t)(DX_ * DY_);

    // Barrier-free o-loop: pure register compute + streaming stores.
    #pragma unroll
    for (int o = 0; o < OG_; ++o) {
        const float Cgo = swt[o][0];
        const float wA0 = swt[o][1];
        const float wA1 = swt[o][2];
        const float wB0 = swt[o][3];
        const float wB1 = swt[o][4];

        float4 bv;  // b[q] at this thread's 4 q positions
        bv.x = wB0 * yl0  + wB1 * yv.y;
        bv.y = wB0 * yv.x + wB1 * yv.z;
        bv.z = wB0 * yv.y + wB1 * yv.w;
        bv.w = wB0 * yv.z + wB1 * yr3;

        float* __restrict__ obase = obase_ng + (size_t)o * (DX_ * DY_);

        #pragma unroll
        for (int it = 0; it < 4; ++it) {
            const int p = pt * PT + it * 4 + r;
            const float s  = Cgo * xp[it];
            const float ap = wA0 * xl[it] + wA1 * xr[it];

            float4 v;
            v.x = fmaf(s, yv.x, ap + bv.x);
            v.y = fmaf(s, yv.y, ap + bv.y);
            v.z = fmaf(s, yv.z, ap + bv.z);
            v.w = fmaf(s, yv.w, ap + bv.w);

            // Streaming store: write-once output, bypass L2 persistence.
            __stcs(reinterpret_cast<float4*>(obase + (size_t)p * DY_) + c, v);
        }
    }
}

extern "C" void kernel_launch(void* const* d_in, const int* in_sizes, int n_in,
                              void* d_out, int out_size)
{
    const float* x  = (const float*)d_in[0];
    const float* y  = (const float*)d_in[1];
    const float* C  = (const float*)d_in[2];
    const float* wA = (const float*)d_in[3];
    const float* wB = (const float*)d_in[4];
    float* out = (float*)d_out;

    const int nblocks = N_ * G_ * (DX_ / PT);  // 1024
    scvc_kernel<<<nblocks, 256>>>(x, y, C, wA, wB, out);
}